// round 1
// baseline (speedup 1.0000x reference)
#include <cuda_runtime.h>

#define BB   4
#define NN   8000
#define CC   64
#define KK   32
#define DD   9
#define NCLS 13
#define BN   (BB*NN)

__device__ float  g_G1[BN*CC];
__device__ float  g_G2[BN*CC];
__device__ float4 g_pts[BN];
__device__ int    g_idx[BN*KK];

__device__ __forceinline__ float inf_f() { return __int_as_float(0x7f800000); }

// ---------------------------------------------------------------------------
// Encoder: feats = relu(x@w1+b1)@w2+b2 ; G1 = feats@f1w ; G2 = feats@f2w
// One thread per point, register-tiled accumulators, activations staged in
// local memory so the 64-deep K loops stay rolled (small I-footprint).
// ---------------------------------------------------------------------------
__global__ __launch_bounds__(256) void encoder_kernel(
    const float* __restrict__ x,
    const float* __restrict__ w1, const float* __restrict__ b1v,
    const float* __restrict__ w2, const float* __restrict__ b2v,
    const float* __restrict__ f1w, const float* __restrict__ f2w)
{
    int g = blockIdx.x * blockDim.x + threadIdx.x;
    if (g >= BN) return;

    float xr[DD];
    #pragma unroll
    for (int d = 0; d < DD; d++) xr[d] = x[g*DD + d];
    g_pts[g] = make_float4(xr[0], xr[1], xr[2],
                           xr[0]*xr[0] + xr[1]*xr[1] + xr[2]*xr[2]);

    float acc[CC];

    // hidden = relu(x @ w1 + b1)
    {
        const float4* bq = (const float4*)b1v;
        #pragma unroll
        for (int c4 = 0; c4 < CC/4; c4++) {
            float4 bv = bq[c4];
            acc[c4*4+0]=bv.x; acc[c4*4+1]=bv.y; acc[c4*4+2]=bv.z; acc[c4*4+3]=bv.w;
        }
        #pragma unroll
        for (int d = 0; d < DD; d++) {
            float xv = xr[d];
            const float4* wv = (const float4*)(w1 + d*CC);
            #pragma unroll
            for (int c4 = 0; c4 < CC/4; c4++) {
                float4 w = wv[c4];
                acc[c4*4+0] = fmaf(xv, w.x, acc[c4*4+0]);
                acc[c4*4+1] = fmaf(xv, w.y, acc[c4*4+1]);
                acc[c4*4+2] = fmaf(xv, w.z, acc[c4*4+2]);
                acc[c4*4+3] = fmaf(xv, w.w, acc[c4*4+3]);
            }
        }
    }
    float hloc[CC];                       // local mem (dynamic read below)
    #pragma unroll
    for (int c = 0; c < CC; c++) hloc[c] = fmaxf(acc[c], 0.f);

    // feats = hidden @ w2 + b2
    {
        const float4* bq = (const float4*)b2v;
        #pragma unroll
        for (int c4 = 0; c4 < CC/4; c4++) {
            float4 bv = bq[c4];
            acc[c4*4+0]=bv.x; acc[c4*4+1]=bv.y; acc[c4*4+2]=bv.z; acc[c4*4+3]=bv.w;
        }
        #pragma unroll 1
        for (int j = 0; j < CC; j++) {
            float hv = hloc[j];
            const float4* wv = (const float4*)(w2 + j*CC);
            #pragma unroll
            for (int c4 = 0; c4 < CC/4; c4++) {
                float4 w = wv[c4];
                acc[c4*4+0] = fmaf(hv, w.x, acc[c4*4+0]);
                acc[c4*4+1] = fmaf(hv, w.y, acc[c4*4+1]);
                acc[c4*4+2] = fmaf(hv, w.z, acc[c4*4+2]);
                acc[c4*4+3] = fmaf(hv, w.w, acc[c4*4+3]);
            }
        }
    }
    float floc[CC];
    #pragma unroll
    for (int c = 0; c < CC; c++) floc[c] = acc[c];

    // G1 = feats @ f1w
    #pragma unroll
    for (int c = 0; c < CC; c++) acc[c] = 0.f;
    #pragma unroll 1
    for (int j = 0; j < CC; j++) {
        float fv = floc[j];
        const float4* wv = (const float4*)(f1w + j*CC);
        #pragma unroll
        for (int c4 = 0; c4 < CC/4; c4++) {
            float4 w = wv[c4];
            acc[c4*4+0] = fmaf(fv, w.x, acc[c4*4+0]);
            acc[c4*4+1] = fmaf(fv, w.y, acc[c4*4+1]);
            acc[c4*4+2] = fmaf(fv, w.z, acc[c4*4+2]);
            acc[c4*4+3] = fmaf(fv, w.w, acc[c4*4+3]);
        }
    }
    {
        float4* o = (float4*)g_G1 + g*(CC/4);
        #pragma unroll
        for (int c4 = 0; c4 < CC/4; c4++)
            o[c4] = make_float4(acc[c4*4+0], acc[c4*4+1], acc[c4*4+2], acc[c4*4+3]);
    }

    // G2 = feats @ f2w
    #pragma unroll
    for (int c = 0; c < CC; c++) acc[c] = 0.f;
    #pragma unroll 1
    for (int j = 0; j < CC; j++) {
        float fv = floc[j];
        const float4* wv = (const float4*)(f2w + j*CC);
        #pragma unroll
        for (int c4 = 0; c4 < CC/4; c4++) {
            float4 w = wv[c4];
            acc[c4*4+0] = fmaf(fv, w.x, acc[c4*4+0]);
            acc[c4*4+1] = fmaf(fv, w.y, acc[c4*4+1]);
            acc[c4*4+2] = fmaf(fv, w.z, acc[c4*4+2]);
            acc[c4*4+3] = fmaf(fv, w.w, acc[c4*4+3]);
        }
    }
    {
        float4* o = (float4*)g_G2 + g*(CC/4);
        #pragma unroll
        for (int c4 = 0; c4 < CC/4; c4++)
            o[c4] = make_float4(acc[c4*4+0], acc[c4*4+1], acc[c4*4+2], acc[c4*4+3]);
    }
}

// ---------------------------------------------------------------------------
// Exact 32-NN per query.  Candidates (xyz,|p|^2) staged in 128KB smem.
// d(i,j) compared via s = |pj|^2 - 2 pi.pj (offset by -|pi|^2, order-preserving).
// Sampled threshold init (10th smallest of 500 stride-16 samples) shrinks
// divergent top-k inserts; exact fallback pass if fewer than 32 fall below it.
// ---------------------------------------------------------------------------
__global__ __launch_bounds__(256) void knn_kernel() {
    extern __shared__ float4 sp[];
    int b = blockIdx.y;
    {
        const float4* src = g_pts + b*NN;
        for (int j = threadIdx.x; j < NN; j += blockDim.x) sp[j] = src[j];
    }
    __syncthreads();

    int q = blockIdx.x * blockDim.x + threadIdx.x;
    if (q >= NN) return;

    float4 me = sp[q];
    float mx = -2.f*me.x, my = -2.f*me.y, mz = -2.f*me.z;
    const float INF = inf_f();

    // ---- prepass: threshold T = 10th smallest of 500 samples ----
    float t[10];
    #pragma unroll
    for (int i = 0; i < 10; i++) t[i] = INF;
    float tw = INF;
    #pragma unroll 1
    for (int k = 0; k < NN/16; k++) {
        float4 c4 = sp[k*16];
        float s = fmaf(c4.x, mx, c4.w);
        s = fmaf(c4.y, my, s);
        s = fmaf(c4.z, mz, s);
        if (s < tw) {
            int am = 0; float mv = t[0];
            #pragma unroll
            for (int i = 1; i < 10; i++) if (t[i] > mv) { mv = t[i]; am = i; }
            #pragma unroll
            for (int i = 0; i < 10; i++) if (i == am) t[i] = s;
            mv = t[0];
            #pragma unroll
            for (int i = 1; i < 10; i++) mv = fmaxf(mv, t[i]);
            tw = mv;
        }
    }

    // ---- main scan: 8 groups x 4 slots; group maxes in registers ----
    float kd[KK]; int ki[KK];    // local memory (rare access)
    float gm[8];
    float Tcur = tw;

    #pragma unroll 1
    for (int pass = 0; pass < 2; pass++) {
        #pragma unroll
        for (int i = 0; i < 8; i++) gm[i] = INF;
        #pragma unroll 1
        for (int i = 0; i < KK; i++) { kd[i] = INF; ki[i] = q; }
        float worst = Tcur;

        #pragma unroll 1
        for (int j = 0; j < NN; j++) {
            float4 c4 = sp[j];
            float s = fmaf(c4.x, mx, c4.w);
            s = fmaf(c4.y, my, s);
            s = fmaf(c4.z, mz, s);
            if (s < worst) {
                int gsel = 0; float gv = gm[0];
                #pragma unroll
                for (int i = 1; i < 8; i++) if (gm[i] > gv) { gv = gm[i]; gsel = i; }
                int base = gsel*4;
                float v0 = kd[base], v1 = kd[base+1], v2 = kd[base+2], v3 = kd[base+3];
                int e = 0; float ev = v0;
                if (v1 > ev) { ev = v1; e = 1; }
                if (v2 > ev) { ev = v2; e = 2; }
                if (v3 > ev) { ev = v3; e = 3; }
                kd[base+e] = s; ki[base+e] = j;
                float ngm = fmaxf(fmaxf(e==0?s:v0, e==1?s:v1),
                                  fmaxf(e==2?s:v2, e==3?s:v3));
                #pragma unroll
                for (int i = 0; i < 8; i++) if (i == gsel) gm[i] = ngm;
                float w8 = gm[0];
                #pragma unroll
                for (int i = 1; i < 8; i++) w8 = fmaxf(w8, gm[i]);
                worst = fminf(Tcur, w8);
            }
        }
        bool ok = true;
        #pragma unroll
        for (int i = 0; i < 8; i++) ok = ok && (gm[i] <= 3.0e38f);
        if (ok) break;
        Tcur = INF;   // rare exact fallback: rerun with no threshold
    }

    int* o = g_idx + (b*NN + q)*KK;
    #pragma unroll 1
    for (int i = 0; i < KK; i++) o[i] = ki[i];
}

// ---------------------------------------------------------------------------
// Fuse (both branches) + classifier.  4 points/block, 64 channel-threads each.
// msg = relu(G[nbr] - G[i] + b) ; max over K ; then 64->32->13 MLP.
// ---------------------------------------------------------------------------
__global__ __launch_bounds__(256) void fuse_kernel(
    const float* __restrict__ f1b, const float* __restrict__ f2b,
    const float* __restrict__ cw1, const float* __restrict__ cb1,
    const float* __restrict__ cw2, const float* __restrict__ cb2,
    float* __restrict__ out)
{
    __shared__ float sfused[4][CC];
    __shared__ float shid[4][CC/2];
    __shared__ int   sidx[4][KK];

    int tid = threadIdx.x;
    int p = tid >> 6, c = tid & 63;
    int g = blockIdx.x*4 + p;              // grid sized exactly: g < BN

    if (c < KK) sidx[p][c] = g_idx[g*KK + c];
    __syncthreads();

    int b = g / NN;
    int rowbase = b*NN;

    float g1i = g_G1[g*CC + c];
    float g2i = g_G2[g*CC + c];
    float bb1 = f1b[c] - g1i;
    float bb2 = f2b[c] - g2i;
    float m1 = 0.f, m2 = 0.f;
    #pragma unroll 8
    for (int k = 0; k < KK; k++) {
        int j = sidx[p][k] + rowbase;
        m1 = fmaxf(m1, g_G1[j*CC + c] + bb1);
        m2 = fmaxf(m2, g_G2[j*CC + c] + bb2);
    }
    sfused[p][c] = m1 + m2;
    __syncthreads();

    if (c < CC/2) {
        float a = cb1[c];
        #pragma unroll
        for (int u = 0; u < CC; u++) a = fmaf(sfused[p][u], cw1[u*(CC/2) + c], a);
        shid[p][c] = fmaxf(a, 0.f);
    }
    __syncthreads();

    if (c < NCLS) {
        float a = cb2[c];
        #pragma unroll
        for (int u = 0; u < CC/2; u++) a = fmaf(shid[p][u], cw2[u*NCLS + c], a);
        out[g*NCLS + c] = a;
    }
}

extern "C" void kernel_launch(void* const* d_in, const int* in_sizes, int n_in,
                              void* d_out, int out_size) {
    const float* x      = (const float*)d_in[0];
    const float* enc_w1 = (const float*)d_in[1];
    const float* enc_b1 = (const float*)d_in[2];
    const float* enc_w2 = (const float*)d_in[3];
    const float* enc_b2 = (const float*)d_in[4];
    const float* f1_w   = (const float*)d_in[5];
    const float* f1_b   = (const float*)d_in[6];
    const float* f2_w   = (const float*)d_in[7];
    const float* f2_b   = (const float*)d_in[8];
    const float* cls_w1 = (const float*)d_in[9];
    const float* cls_b1 = (const float*)d_in[10];
    const float* cls_w2 = (const float*)d_in[11];
    const float* cls_b2 = (const float*)d_in[12];

    encoder_kernel<<<(BN + 255)/256, 256>>>(x, enc_w1, enc_b1, enc_w2, enc_b2,
                                            f1_w, f2_w);

    const int knn_smem = NN * (int)sizeof(float4);   // 128000 B
    cudaFuncSetAttribute(knn_kernel, cudaFuncAttributeMaxDynamicSharedMemorySize,
                         knn_smem);
    dim3 kg((NN + 255)/256, BB);
    knn_kernel<<<kg, 256, knn_smem>>>();

    fuse_kernel<<<BN/4, 256>>>(f1_b, f2_b, cls_w1, cls_b1, cls_w2, cls_b2,
                               (float*)d_out);
}

// round 2
// speedup vs baseline: 1.3679x; 1.3679x over previous
#include <cuda_runtime.h>

#define BB   4
#define NN   8000
#define CC   64
#define KK   32
#define DD   9
#define NCLS 13
#define BN   (BB*NN)

#define CAP      320      // per-thread candidate buffer slots
#define TPB_KNN  224      // 7 warps; grid (36,4)=144 blocks ~ 148 SMs
#define ENC_PTS  64       // points per encoder block (4 workers each)

__device__ float  g_G1[BN*CC];
__device__ float  g_G2[BN*CC];
__device__ float4 g_pts[BN];
__device__ int    g_idx[BN*KK];

__device__ __forceinline__ float inf_f() { return __int_as_float(0x7f800000); }

// ---------------------------------------------------------------------------
// Encoder: feats = relu(x@w1+b1)@w2+b2 ; G1 = feats@f1w ; G2 = feats@f2w
// 64 points/block, 4 worker-threads per point (16 channels each), layer
// activations exchanged via shared memory. ~55 regs -> high occupancy.
// ---------------------------------------------------------------------------
__global__ __launch_bounds__(256) void encoder_kernel(
    const float* __restrict__ x,
    const float* __restrict__ w1, const float* __restrict__ b1v,
    const float* __restrict__ w2, const float* __restrict__ b2v,
    const float* __restrict__ f1w, const float* __restrict__ f2w)
{
    __shared__ float sx[ENC_PTS][12];
    __shared__ float sh[ENC_PTS][68];
    __shared__ float sf[ENC_PTS][68];

    int tid = threadIdx.x;
    int p = tid >> 2, t = tid & 3;
    int g0 = blockIdx.x * ENC_PTS;          // grid = BN/ENC_PTS exactly

    for (int i = tid; i < ENC_PTS*DD; i += 256) {
        int pp = i / DD, d = i % DD;
        sx[pp][d] = x[(g0 + pp)*DD + d];
    }
    __syncthreads();

    int g = g0 + p;
    if (t == 0) {
        float a = sx[p][0], b = sx[p][1], c = sx[p][2];
        g_pts[g] = make_float4(a, b, c, a*a + b*b + c*c);
    }

    float acc[16];

    // layer 1: hidden = relu(x @ w1 + b1)   (9 -> 64)
    {
        const float4* bq = (const float4*)b1v + t*4;
        #pragma unroll
        for (int c4 = 0; c4 < 4; c4++) {
            float4 bv = bq[c4];
            acc[c4*4+0]=bv.x; acc[c4*4+1]=bv.y; acc[c4*4+2]=bv.z; acc[c4*4+3]=bv.w;
        }
        #pragma unroll
        for (int d = 0; d < DD; d++) {
            float xv = sx[p][d];
            const float4* wv = (const float4*)(w1 + d*CC + t*16);
            #pragma unroll
            for (int c4 = 0; c4 < 4; c4++) {
                float4 w = wv[c4];
                acc[c4*4+0] = fmaf(xv, w.x, acc[c4*4+0]);
                acc[c4*4+1] = fmaf(xv, w.y, acc[c4*4+1]);
                acc[c4*4+2] = fmaf(xv, w.z, acc[c4*4+2]);
                acc[c4*4+3] = fmaf(xv, w.w, acc[c4*4+3]);
            }
        }
        #pragma unroll
        for (int c = 0; c < 16; c++) sh[p][t*16 + c] = fmaxf(acc[c], 0.f);
    }
    __syncthreads();

    // layer 2: feats = hidden @ w2 + b2   (64 -> 64)
    {
        const float4* bq = (const float4*)b2v + t*4;
        #pragma unroll
        for (int c4 = 0; c4 < 4; c4++) {
            float4 bv = bq[c4];
            acc[c4*4+0]=bv.x; acc[c4*4+1]=bv.y; acc[c4*4+2]=bv.z; acc[c4*4+3]=bv.w;
        }
        #pragma unroll 4
        for (int j = 0; j < CC; j++) {
            float hv = sh[p][j];
            const float4* wv = (const float4*)(w2 + j*CC + t*16);
            #pragma unroll
            for (int c4 = 0; c4 < 4; c4++) {
                float4 w = wv[c4];
                acc[c4*4+0] = fmaf(hv, w.x, acc[c4*4+0]);
                acc[c4*4+1] = fmaf(hv, w.y, acc[c4*4+1]);
                acc[c4*4+2] = fmaf(hv, w.z, acc[c4*4+2]);
                acc[c4*4+3] = fmaf(hv, w.w, acc[c4*4+3]);
            }
        }
        #pragma unroll
        for (int c = 0; c < 16; c++) sf[p][t*16 + c] = acc[c];
    }
    __syncthreads();

    // G1 = feats @ f1w
    {
        #pragma unroll
        for (int c = 0; c < 16; c++) acc[c] = 0.f;
        #pragma unroll 4
        for (int j = 0; j < CC; j++) {
            float fv = sf[p][j];
            const float4* wv = (const float4*)(f1w + j*CC + t*16);
            #pragma unroll
            for (int c4 = 0; c4 < 4; c4++) {
                float4 w = wv[c4];
                acc[c4*4+0] = fmaf(fv, w.x, acc[c4*4+0]);
                acc[c4*4+1] = fmaf(fv, w.y, acc[c4*4+1]);
                acc[c4*4+2] = fmaf(fv, w.z, acc[c4*4+2]);
                acc[c4*4+3] = fmaf(fv, w.w, acc[c4*4+3]);
            }
        }
        float4* o = (float4*)(g_G1 + g*CC + t*16);
        #pragma unroll
        for (int c4 = 0; c4 < 4; c4++)
            o[c4] = make_float4(acc[c4*4+0], acc[c4*4+1], acc[c4*4+2], acc[c4*4+3]);
    }

    // G2 = feats @ f2w
    {
        #pragma unroll
        for (int c = 0; c < 16; c++) acc[c] = 0.f;
        #pragma unroll 4
        for (int j = 0; j < CC; j++) {
            float fv = sf[p][j];
            const float4* wv = (const float4*)(f2w + j*CC + t*16);
            #pragma unroll
            for (int c4 = 0; c4 < 4; c4++) {
                float4 w = wv[c4];
                acc[c4*4+0] = fmaf(fv, w.x, acc[c4*4+0]);
                acc[c4*4+1] = fmaf(fv, w.y, acc[c4*4+1]);
                acc[c4*4+2] = fmaf(fv, w.z, acc[c4*4+2]);
                acc[c4*4+3] = fmaf(fv, w.w, acc[c4*4+3]);
            }
        }
        float4* o = (float4*)(g_G2 + g*CC + t*16);
        #pragma unroll
        for (int c4 = 0; c4 < 4; c4++)
            o[c4] = make_float4(acc[c4*4+0], acc[c4*4+1], acc[c4*4+2], acc[c4*4+3]);
    }
}

// ---------------------------------------------------------------------------
// Exact 32-smallest of buf[0..cnt) via 8x4 group-max insert. Writes the 32
// survivors back to buf[0..32) and ki/kd; returns worst (32nd smallest).
// ---------------------------------------------------------------------------
__device__ __noinline__ float compact32(unsigned long long* buf, int cnt,
                                        float* kd, int* ki)
{
    const float INF = inf_f();
    float gm[8];
    #pragma unroll
    for (int i = 0; i < 8; i++) gm[i] = INF;
    #pragma unroll 1
    for (int i = 0; i < KK; i++) { kd[i] = INF; ki[i] = 0; }
    float worst = INF;

    #pragma unroll 1
    for (int tix = 0; tix < cnt; tix++) {
        unsigned long long v = buf[tix];
        float s = __uint_as_float((unsigned)(v >> 32));
        if (s < worst) {
            int id = (int)(unsigned)v;
            int gsel = 0; float gv = gm[0];
            #pragma unroll
            for (int i = 1; i < 8; i++) if (gm[i] > gv) { gv = gm[i]; gsel = i; }
            int base = gsel*4;
            float v0 = kd[base], v1 = kd[base+1], v2 = kd[base+2], v3 = kd[base+3];
            int e = 0; float ev = v0;
            if (v1 > ev) { ev = v1; e = 1; }
            if (v2 > ev) { ev = v2; e = 2; }
            if (v3 > ev) { ev = v3; e = 3; }
            kd[base+e] = s; ki[base+e] = id;
            float ngm = fmaxf(fmaxf(e==0?s:v0, e==1?s:v1),
                              fmaxf(e==2?s:v2, e==3?s:v3));
            #pragma unroll
            for (int i = 0; i < 8; i++) if (i == gsel) gm[i] = ngm;
            float w8 = gm[0];
            #pragma unroll
            for (int i = 1; i < 8; i++) w8 = fmaxf(w8, gm[i]);
            worst = w8;
        }
    }
    #pragma unroll 1
    for (int i = 0; i < KK; i++)
        buf[i] = ((unsigned long long)__float_as_uint(kd[i]) << 32) |
                 (unsigned)ki[i];
    return worst;
}

// ---------------------------------------------------------------------------
// Exact 32-NN. Candidates staged in 128KB smem. Compare s = |pj|^2 - 2 pi.pj
// (order-preserving shift of the squared distance). Sampled threshold
// (10th-smallest of 500) -> cheap predicated appends into a local buffer,
// rare exact compaction on overflow, exact final selection; exact full-rescan
// fallback if fewer than 32 survivors (P ~ 4e-5 per query).
// ---------------------------------------------------------------------------
__global__ __launch_bounds__(TPB_KNN) void knn_kernel() {
    extern __shared__ float4 sp[];
    int b = blockIdx.y;
    for (int j = threadIdx.x; j < NN; j += TPB_KNN) sp[j] = g_pts[b*NN + j];
    __syncthreads();

    int q = blockIdx.x * TPB_KNN + threadIdx.x;
    if (q >= NN) return;

    float4 me = sp[q];
    float mx = -2.f*me.x, my = -2.f*me.y, mz = -2.f*me.z;
    const float INF = inf_f();

    // ---- prepass: T0 = 10th smallest of 500 stride-16 samples ----
    float t[10];
    #pragma unroll
    for (int i = 0; i < 10; i++) t[i] = INF;
    float tw = INF;
    #pragma unroll 1
    for (int k = 0; k < 125; k++) {
        float s4[4];
        #pragma unroll
        for (int u = 0; u < 4; u++) {
            float4 c = sp[k*64 + u*16];
            float s = fmaf(c.x, mx, c.w);
            s = fmaf(c.y, my, s);
            s4[u] = fmaf(c.z, mz, s);
        }
        float mn = fminf(fminf(s4[0], s4[1]), fminf(s4[2], s4[3]));
        if (mn < tw) {
            #pragma unroll
            for (int u = 0; u < 4; u++) {
                float s = s4[u];
                if (s < tw) {
                    int am = 0; float mv = t[0];
                    #pragma unroll
                    for (int i = 1; i < 10; i++) if (t[i] > mv) { mv = t[i]; am = i; }
                    #pragma unroll
                    for (int i = 0; i < 10; i++) if (i == am) t[i] = s;
                    mv = t[0];
                    #pragma unroll
                    for (int i = 1; i < 10; i++) mv = fmaxf(mv, t[i]);
                    tw = mv;
                }
            }
        }
    }

    // ---- main scan: predicated appends, rare compaction ----
    unsigned long long buf[CAP];
    float kd[KK]; int ki[KK];
    float T0 = tw;
    int cnt = 0;

    #pragma unroll 1
    for (int pass = 0; pass < 2; pass++) {
        cnt = 0;
        float thr = T0;
        #pragma unroll 1
        for (int jg = 0; jg < NN/8; jg++) {
            int j0 = jg*8;
            float s[8];
            #pragma unroll
            for (int u = 0; u < 8; u++) {
                float4 c = sp[j0 + u];
                float ss = fmaf(c.x, mx, c.w);
                ss = fmaf(c.y, my, ss);
                s[u] = fmaf(c.z, mz, ss);
            }
            float m01 = fminf(s[0], s[1]), m23 = fminf(s[2], s[3]);
            float m45 = fminf(s[4], s[5]), m67 = fminf(s[6], s[7]);
            float mn = fminf(fminf(m01, m23), fminf(m45, m67));
            if (mn < thr) {
                #pragma unroll
                for (int u = 0; u < 8; u++) {
                    if (s[u] < thr) {
                        buf[cnt] = ((unsigned long long)__float_as_uint(s[u]) << 32)
                                   | (unsigned)(j0 + u);
                        cnt++;
                    }
                }
                if (cnt >= CAP - 8) {
                    float w2 = compact32(buf, cnt, kd, ki);
                    thr = fminf(thr, w2);
                    cnt = KK;
                }
            }
        }
        if (cnt >= KK) break;
        T0 = INF;          // exact fallback: rescan everything
    }

    compact32(buf, cnt, kd, ki);
    int* o = g_idx + (b*NN + q)*KK;
    #pragma unroll 1
    for (int i = 0; i < KK; i++) o[i] = ki[i];
}

// ---------------------------------------------------------------------------
// Fuse (both branches) + classifier. msg = relu(G[nbr]-G[i]+b); max over K;
// fused = m1+m2; then 64->32->13 MLP. 4 points/block, 64 channel-threads.
// ---------------------------------------------------------------------------
__global__ __launch_bounds__(256) void fuse_kernel(
    const float* __restrict__ f1b, const float* __restrict__ f2b,
    const float* __restrict__ cw1, const float* __restrict__ cb1,
    const float* __restrict__ cw2, const float* __restrict__ cb2,
    float* __restrict__ out)
{
    __shared__ float sfused[4][CC];
    __shared__ float shid[4][CC/2];
    __shared__ int   sidx[4][KK];

    int tid = threadIdx.x;
    int p = tid >> 6, c = tid & 63;
    int g = blockIdx.x*4 + p;

    if (c < KK) sidx[p][c] = g_idx[g*KK + c];
    __syncthreads();

    int b = g / NN;
    int rowbase = b*NN;

    float g1i = g_G1[g*CC + c];
    float g2i = g_G2[g*CC + c];
    float bb1 = f1b[c] - g1i;
    float bb2 = f2b[c] - g2i;
    float m1 = 0.f, m2 = 0.f;
    #pragma unroll 8
    for (int k = 0; k < KK; k++) {
        int j = sidx[p][k] + rowbase;
        m1 = fmaxf(m1, g_G1[j*CC + c] + bb1);
        m2 = fmaxf(m2, g_G2[j*CC + c] + bb2);
    }
    sfused[p][c] = m1 + m2;
    __syncthreads();

    if (c < CC/2) {
        float a = cb1[c];
        #pragma unroll
        for (int u = 0; u < CC; u++) a = fmaf(sfused[p][u], cw1[u*(CC/2) + c], a);
        shid[p][c] = fmaxf(a, 0.f);
    }
    __syncthreads();

    if (c < NCLS) {
        float a = cb2[c];
        #pragma unroll
        for (int u = 0; u < CC/2; u++) a = fmaf(shid[p][u], cw2[u*NCLS + c], a);
        out[g*NCLS + c] = a;
    }
}

extern "C" void kernel_launch(void* const* d_in, const int* in_sizes, int n_in,
                              void* d_out, int out_size) {
    const float* x      = (const float*)d_in[0];
    const float* enc_w1 = (const float*)d_in[1];
    const float* enc_b1 = (const float*)d_in[2];
    const float* enc_w2 = (const float*)d_in[3];
    const float* enc_b2 = (const float*)d_in[4];
    const float* f1_w   = (const float*)d_in[5];
    const float* f1_b   = (const float*)d_in[6];
    const float* f2_w   = (const float*)d_in[7];
    const float* f2_b   = (const float*)d_in[8];
    const float* cls_w1 = (const float*)d_in[9];
    const float* cls_b1 = (const float*)d_in[10];
    const float* cls_w2 = (const float*)d_in[11];
    const float* cls_b2 = (const float*)d_in[12];

    encoder_kernel<<<BN/ENC_PTS, 256>>>(x, enc_w1, enc_b1, enc_w2, enc_b2,
                                        f1_w, f2_w);

    const int knn_smem = NN * (int)sizeof(float4);   // 128000 B
    cudaFuncSetAttribute(knn_kernel, cudaFuncAttributeMaxDynamicSharedMemorySize,
                         knn_smem);
    dim3 kg((NN + TPB_KNN - 1)/TPB_KNN, BB);
    knn_kernel<<<kg, TPB_KNN, knn_smem>>>();

    fuse_kernel<<<BN/4, 256>>>(f1_b, f2_b, cls_w1, cls_b1, cls_w2, cls_b2,
                               (float*)d_out);
}